// round 1
// baseline (speedup 1.0000x reference)
#include <cuda_runtime.h>
#include <math.h>

#define EMB   256
#define HEADS 8
#define HDIM  32
#define BATCH 4
#define SEQ   2048
#define MROWS (BATCH*SEQ)   // 8192

// Scratch (static __device__ — no allocation)
__device__ float g_Q[BATCH*HEADS*SEQ*HDIM];   // [b][h][n][d], pre-scaled by 1/16
__device__ float g_K[BATCH*HEADS*SEQ*HDIM];
__device__ float g_V[BATCH*HEADS*SEQ*HDIM];
__device__ float g_O[MROWS*EMB];              // [b][n][e] attention output

// ---------------------------------------------------------------------------
// Tiled GEMM: C[M,N] = A[M,K] @ W[N,K]^T (+bias). BM=BN=64, BK=16, 256 thr,
// 4x4 micro-tile per thread. Fused QKV variant shares the A tile across 3 Ws.
// ---------------------------------------------------------------------------
#define BM 64
#define BN 64
#define BK 16
#define SPAD 4   // smem row pad (stride 68 keeps float4 alignment, kills conflicts)

__global__ __launch_bounds__(256) void qkv_kernel(
    const float* __restrict__ x,
    const float* __restrict__ Wq, const float* __restrict__ bq,
    const float* __restrict__ Wk, const float* __restrict__ bk,
    const float* __restrict__ Wv, const float* __restrict__ bv)
{
    __shared__ float As[BK][BM+SPAD];
    __shared__ float Qs[BK][BN+SPAD];
    __shared__ float Ks[BK][BN+SPAD];
    __shared__ float Vs[BK][BN+SPAD];

    const int tid = threadIdx.x;
    const int m0 = blockIdx.x * BM;
    const int n0 = blockIdx.y * BN;
    const int tx = tid & 15;        // 0..15 -> cols
    const int ty = tid >> 4;        // 0..15 -> rows

    float accq[4][4] = {}, acck[4][4] = {}, accv[4][4] = {};

    for (int k0 = 0; k0 < EMB; k0 += BK) {
        // Load A tile: 64 rows x 16 k (1024 floats / 256 thr = 4 each)
        #pragma unroll
        for (int it = 0; it < 4; it++) {
            int i = it * 256 + tid;
            int m = i >> 4, k = i & 15;
            As[k][m] = x[(size_t)(m0 + m) * EMB + k0 + k];
        }
        // Load 3 weight tiles: W[n0+n][k0+k]
        #pragma unroll
        for (int it = 0; it < 4; it++) {
            int i = it * 256 + tid;
            int n = i >> 4, k = i & 15;
            size_t off = (size_t)(n0 + n) * EMB + k0 + k;
            Qs[k][n] = Wq[off];
            Ks[k][n] = Wk[off];
            Vs[k][n] = Wv[off];
        }
        __syncthreads();

        #pragma unroll
        for (int k = 0; k < BK; k++) {
            float4 a4 = *(const float4*)&As[k][ty * 4];
            float4 q4 = *(const float4*)&Qs[k][tx * 4];
            float4 k4 = *(const float4*)&Ks[k][tx * 4];
            float4 v4 = *(const float4*)&Vs[k][tx * 4];
            float av[4] = {a4.x, a4.y, a4.z, a4.w};
            float qv[4] = {q4.x, q4.y, q4.z, q4.w};
            float kv[4] = {k4.x, k4.y, k4.z, k4.w};
            float vv[4] = {v4.x, v4.y, v4.z, v4.w};
            #pragma unroll
            for (int i = 0; i < 4; i++)
                #pragma unroll
                for (int j = 0; j < 4; j++) {
                    accq[i][j] += av[i] * qv[j];
                    acck[i][j] += av[i] * kv[j];
                    accv[i][j] += av[i] * vv[j];
                }
        }
        __syncthreads();
    }

    // Epilogue: bias, scatter to [b][h][n][d]; pre-scale Q by 1/sqrt(EMB)=1/16
    #pragma unroll
    for (int i = 0; i < 4; i++) {
        int gm = m0 + ty * 4 + i;           // global row = b*SEQ + n
        int b = gm / SEQ, n = gm % SEQ;
        #pragma unroll
        for (int j = 0; j < 4; j++) {
            int col = n0 + tx * 4 + j;      // = h*32 + d
            int h = col >> 5, d = col & 31;
            size_t idx = (((size_t)(b * HEADS + h) * SEQ) + n) * HDIM + d;
            g_Q[idx] = (accq[i][j] + bq[col]) * 0.0625f;
            g_K[idx] =  acck[i][j] + bk[col];
            g_V[idx] =  accv[i][j] + bv[col];
        }
    }
}

// ---------------------------------------------------------------------------
// Attention: 1 thread = 1 query row. q/o/s in registers, K/V tiles (32x32) in
// smem, broadcast LDS.128 reads. Online softmax.
// ---------------------------------------------------------------------------
#define KTILE 32

__global__ __launch_bounds__(128) void attn_kernel()
{
    const int bh   = blockIdx.y;                         // b*HEADS + h
    const int qrow = blockIdx.x * 128 + threadIdx.x;     // n
    const int tid  = threadIdx.x;

    __shared__ float Ksm[KTILE][HDIM];
    __shared__ float Vsm[KTILE][HDIM];

    const float* __restrict__ Qp = g_Q + (((size_t)bh * SEQ) + qrow) * HDIM;
    const float* __restrict__ Kb = g_K + (size_t)bh * SEQ * HDIM;
    const float* __restrict__ Vb = g_V + (size_t)bh * SEQ * HDIM;

    float q[HDIM], o[HDIM];
    #pragma unroll
    for (int d = 0; d < HDIM; d++) { q[d] = Qp[d]; o[d] = 0.f; }
    float mrun = -1e30f, lrun = 0.f;

    for (int t0 = 0; t0 < SEQ; t0 += KTILE) {
        __syncthreads();
        // Stage K/V tile: 1024 floats each = 256 float4 each; 128 threads x 2
        {
            const float4* ks = (const float4*)(Kb + (size_t)t0 * HDIM);
            const float4* vs = (const float4*)(Vb + (size_t)t0 * HDIM);
            float4* kd = (float4*)&Ksm[0][0];
            float4* vd = (float4*)&Vsm[0][0];
            kd[tid]       = ks[tid];
            kd[tid + 128] = ks[tid + 128];
            vd[tid]       = vs[tid];
            vd[tid + 128] = vs[tid + 128];
        }
        __syncthreads();

        float s[KTILE];
        float tmax = -1e30f;
        #pragma unroll
        for (int j = 0; j < KTILE; j++) {
            const float4* kr = (const float4*)Ksm[j];
            float acc = 0.f;
            #pragma unroll
            for (int d4 = 0; d4 < HDIM / 4; d4++) {
                float4 kv = kr[d4];
                acc += q[d4*4+0] * kv.x;
                acc += q[d4*4+1] * kv.y;
                acc += q[d4*4+2] * kv.z;
                acc += q[d4*4+3] * kv.w;
            }
            s[j] = acc;
            tmax = fmaxf(tmax, acc);
        }

        float mnew = fmaxf(mrun, tmax);
        float corr = __expf(mrun - mnew);
        lrun *= corr;
        #pragma unroll
        for (int d = 0; d < HDIM; d++) o[d] *= corr;

        #pragma unroll
        for (int j = 0; j < KTILE; j++) {
            float p = __expf(s[j] - mnew);
            lrun += p;
            const float4* vr = (const float4*)Vsm[j];
            #pragma unroll
            for (int d4 = 0; d4 < HDIM / 4; d4++) {
                float4 vv = vr[d4];
                o[d4*4+0] += p * vv.x;
                o[d4*4+1] += p * vv.y;
                o[d4*4+2] += p * vv.z;
                o[d4*4+3] += p * vv.w;
            }
        }
        mrun = mnew;
    }

    const float inv = 1.f / lrun;
    const int b = bh / HEADS, h = bh % HEADS;
    float* Op = g_O + ((size_t)(b * SEQ + qrow)) * EMB + h * HDIM;
    #pragma unroll
    for (int d = 0; d < HDIM; d++) Op[d] = o[d] * inv;
}

// ---------------------------------------------------------------------------
// Output projection: out = g_O @ Wo^T + bo
// ---------------------------------------------------------------------------
__global__ __launch_bounds__(256) void proj_kernel(
    const float* __restrict__ Wo, const float* __restrict__ bo,
    float* __restrict__ out)
{
    __shared__ float As[BK][BM+SPAD];
    __shared__ float Ws[BK][BN+SPAD];

    const int tid = threadIdx.x;
    const int m0 = blockIdx.x * BM;
    const int n0 = blockIdx.y * BN;
    const int tx = tid & 15;
    const int ty = tid >> 4;

    float acc[4][4] = {};

    for (int k0 = 0; k0 < EMB; k0 += BK) {
        #pragma unroll
        for (int it = 0; it < 4; it++) {
            int i = it * 256 + tid;
            int m = i >> 4, k = i & 15;
            As[k][m] = g_O[(size_t)(m0 + m) * EMB + k0 + k];
        }
        #pragma unroll
        for (int it = 0; it < 4; it++) {
            int i = it * 256 + tid;
            int n = i >> 4, k = i & 15;
            Ws[k][n] = Wo[(size_t)(n0 + n) * EMB + k0 + k];
        }
        __syncthreads();

        #pragma unroll
        for (int k = 0; k < BK; k++) {
            float4 a4 = *(const float4*)&As[k][ty * 4];
            float4 w4 = *(const float4*)&Ws[k][tx * 4];
            float av[4] = {a4.x, a4.y, a4.z, a4.w};
            float wv[4] = {w4.x, w4.y, w4.z, w4.w};
            #pragma unroll
            for (int i = 0; i < 4; i++)
                #pragma unroll
                for (int j = 0; j < 4; j++)
                    acc[i][j] += av[i] * wv[j];
        }
        __syncthreads();
    }

    #pragma unroll
    for (int i = 0; i < 4; i++) {
        int gm = m0 + ty * 4 + i;
        #pragma unroll
        for (int j = 0; j < 4; j++) {
            int col = n0 + tx * 4 + j;
            out[(size_t)gm * EMB + col] = acc[i][j] + bo[col];
        }
    }
}

// ---------------------------------------------------------------------------
extern "C" void kernel_launch(void* const* d_in, const int* in_sizes, int n_in,
                              void* d_out, int out_size)
{
    const float* x  = (const float*)d_in[0];
    const float* Wq = (const float*)d_in[1];
    const float* bq = (const float*)d_in[2];
    const float* Wk = (const float*)d_in[3];
    const float* bk = (const float*)d_in[4];
    const float* Wv = (const float*)d_in[5];
    const float* bv = (const float*)d_in[6];
    const float* Wo = (const float*)d_in[7];
    const float* bo = (const float*)d_in[8];
    float* out = (float*)d_out;

    dim3 gemm_grid(MROWS / BM, EMB / BN);   // (128, 4)
    qkv_kernel<<<gemm_grid, 256>>>(x, Wq, bq, Wk, bk, Wv, bv);

    dim3 attn_grid(SEQ / 128, BATCH * HEADS);  // (16, 32)
    attn_kernel<<<attn_grid, 128>>>();

    proj_kernel<<<gemm_grid, 256>>>(Wo, bo, out);
}

// round 4
// speedup vs baseline: 2.6141x; 2.6141x over previous
#include <cuda_runtime.h>
#include <cstdint>
#include <math.h>

#define EMB   256
#define HEADS 8
#define HDIM  32
#define BATCH 4
#define SEQ   2048
#define MROWS (BATCH*SEQ)   // 8192

// Scratch (static __device__ — no allocation)
__device__ float g_Q[BATCH*HEADS*SEQ*HDIM];   // [b][h][n][d], pre-scaled by 1/16
__device__ float g_K[BATCH*HEADS*SEQ*HDIM];   // [b][h][n][d]
__device__ float g_V[BATCH*HEADS*SEQ*HDIM];   // [b][h][n][d]
__device__ float g_O[MROWS*EMB];              // [b][n][e] attention output

// ---------------------------------------------------------------------------
__device__ __forceinline__ uint32_t f2tf32(float f) {
    uint32_t u;
    asm("cvt.rna.tf32.f32 %0, %1;" : "=r"(u) : "f"(f));
    return u;
}
__device__ __forceinline__ void mma_tf32(float c[4], const uint32_t a[4],
                                         uint32_t b0, uint32_t b1) {
    asm volatile(
        "mma.sync.aligned.m16n8k8.row.col.f32.tf32.tf32.f32 "
        "{%0,%1,%2,%3}, {%4,%5,%6,%7}, {%8,%9}, {%0,%1,%2,%3};"
        : "+f"(c[0]), "+f"(c[1]), "+f"(c[2]), "+f"(c[3])
        : "r"(a[0]), "r"(a[1]), "r"(a[2]), "r"(a[3]), "r"(b0), "r"(b1));
}

// ===========================================================================
// QKV projection (fp32 tiled GEMM, fused 3 weights)
// ===========================================================================
#define BM 64
#define BN 64
#define BK 16
#define SPAD 4

__global__ __launch_bounds__(256) void qkv_kernel(
    const float* __restrict__ x,
    const float* __restrict__ Wq, const float* __restrict__ bq,
    const float* __restrict__ Wk, const float* __restrict__ bk,
    const float* __restrict__ Wv, const float* __restrict__ bv)
{
    __shared__ float As[BK][BM+SPAD];
    __shared__ float Qs[BK][BN+SPAD];
    __shared__ float Ks[BK][BN+SPAD];
    __shared__ float Vs[BK][BN+SPAD];

    const int tid = threadIdx.x;
    const int m0 = blockIdx.x * BM;
    const int n0 = blockIdx.y * BN;
    const int tx = tid & 15;
    const int ty = tid >> 4;

    float accq[4][4] = {}, acck[4][4] = {}, accv[4][4] = {};

    for (int k0 = 0; k0 < EMB; k0 += BK) {
        #pragma unroll
        for (int it = 0; it < 4; it++) {
            int i = it * 256 + tid;
            int m = i >> 4, k = i & 15;
            As[k][m] = x[(size_t)(m0 + m) * EMB + k0 + k];
        }
        #pragma unroll
        for (int it = 0; it < 4; it++) {
            int i = it * 256 + tid;
            int n = i >> 4, k = i & 15;
            size_t off = (size_t)(n0 + n) * EMB + k0 + k;
            Qs[k][n] = Wq[off];
            Ks[k][n] = Wk[off];
            Vs[k][n] = Wv[off];
        }
        __syncthreads();
        #pragma unroll
        for (int k = 0; k < BK; k++) {
            float4 a4 = *(const float4*)&As[k][ty * 4];
            float4 q4 = *(const float4*)&Qs[k][tx * 4];
            float4 k4 = *(const float4*)&Ks[k][tx * 4];
            float4 v4 = *(const float4*)&Vs[k][tx * 4];
            float av[4] = {a4.x, a4.y, a4.z, a4.w};
            float qv[4] = {q4.x, q4.y, q4.z, q4.w};
            float kv[4] = {k4.x, k4.y, k4.z, k4.w};
            float vv[4] = {v4.x, v4.y, v4.z, v4.w};
            #pragma unroll
            for (int i = 0; i < 4; i++)
                #pragma unroll
                for (int j = 0; j < 4; j++) {
                    accq[i][j] += av[i] * qv[j];
                    acck[i][j] += av[i] * kv[j];
                    accv[i][j] += av[i] * vv[j];
                }
        }
        __syncthreads();
    }

    #pragma unroll
    for (int i = 0; i < 4; i++) {
        int gm = m0 + ty * 4 + i;
        int b = gm / SEQ, n = gm % SEQ;
        #pragma unroll
        for (int j = 0; j < 4; j++) {
            int col = n0 + tx * 4 + j;      // h*32 + d
            int h = col >> 5, d = col & 31;
            size_t idx = (((size_t)(b * HEADS + h) * SEQ) + n) * HDIM + d;
            g_Q[idx] = (accq[i][j] + bq[col]) * 0.0625f;
            g_K[idx] =  acck[i][j] + bk[col];
            g_V[idx] =  accv[i][j] + bv[col];
        }
    }
}

// ===========================================================================
// Flash attention with mma.sync tf32 (sm_100-compatible tensor path).
// Grid (SEQ/64, B*H) = (32, 32). 128 threads = 4 warps; each warp owns 16
// query rows. K/V tiles of 64x32 in smem (row stride 36); P strip 64x64 in
// smem with its own stride 68 (64 cols + pad, conflict-free fragments).
// ===========================================================================
#define QT   64
#define KT   64
#define NIT  (SEQ / KT)   // 32
#define STR  36           // smem row stride for 32-col tiles (floats)
#define PSTR 68           // smem row stride for 64-col P strip (floats)

__global__ __launch_bounds__(128) void attn_mma_kernel()
{
    __shared__ float sQ[QT * STR];
    __shared__ float sK[KT * STR];
    __shared__ float sV[KT * STR];
    __shared__ float sP[QT * PSTR];   // 64 x 64 (+pad), per-warp 16-row strips

    const int tid  = threadIdx.x;
    const int lane = tid & 31;
    const int w    = tid >> 5;
    const int g    = lane >> 2;       // group id (row within fragment)
    const int q    = lane & 3;        // thread in group (col)
    const int bh   = blockIdx.y;
    const int q0   = blockIdx.x * QT;

    const float* Qg = g_Q + ((size_t)bh * SEQ + q0) * HDIM;
    const float* Kg = g_K + (size_t)bh * SEQ * HDIM;
    const float* Vg = g_V + (size_t)bh * SEQ * HDIM;

    // ---- Stage Q block [64 x 32] ----
    #pragma unroll
    for (int i = 0; i < 4; i++) {
        int f4 = tid + i * 128;            // 0..511
        int r = f4 >> 3, c4 = f4 & 7;
        float4 v = *(const float4*)(Qg + r * HDIM + c4 * 4);
        *(float4*)&sQ[r * STR + c4 * 4] = v;
    }
    __syncthreads();

    // ---- Q A-fragments (tf32), 4 k-chunks ----
    const int wr = w * 16;
    uint32_t qa[4][4];
    #pragma unroll
    for (int kt = 0; kt < 4; kt++) {
        qa[kt][0] = f2tf32(sQ[(wr + g    ) * STR + kt * 8 + q    ]);
        qa[kt][1] = f2tf32(sQ[(wr + g + 8) * STR + kt * 8 + q    ]);
        qa[kt][2] = f2tf32(sQ[(wr + g    ) * STR + kt * 8 + q + 4]);
        qa[kt][3] = f2tf32(sQ[(wr + g + 8) * STR + kt * 8 + q + 4]);
    }

    float o[4][4] = {};                 // O strip 16x32 (4 n-tiles)
    float m0 = -1e30f, m1 = -1e30f;     // running max for rows g, g+8
    float l0 = 0.f,    l1 = 0.f;

    for (int t = 0; t < NIT; t++) {
        const int t0 = t * KT;
        __syncthreads();
        // ---- Stage K/V tiles [64 x 32], tf32-rounded ----
        #pragma unroll
        for (int i = 0; i < 4; i++) {
            int f4 = tid + i * 128;
            int r = f4 >> 3, c4 = f4 & 7;
            float4 kv = *(const float4*)(Kg + (size_t)(t0 + r) * HDIM + c4 * 4);
            float4 vv = *(const float4*)(Vg + (size_t)(t0 + r) * HDIM + c4 * 4);
            float4 ko, vo;
            ko.x = __uint_as_float(f2tf32(kv.x)); ko.y = __uint_as_float(f2tf32(kv.y));
            ko.z = __uint_as_float(f2tf32(kv.z)); ko.w = __uint_as_float(f2tf32(kv.w));
            vo.x = __uint_as_float(f2tf32(vv.x)); vo.y = __uint_as_float(f2tf32(vv.y));
            vo.z = __uint_as_float(f2tf32(vv.z)); vo.w = __uint_as_float(f2tf32(vv.w));
            *(float4*)&sK[r * STR + c4 * 4] = ko;
            *(float4*)&sV[r * STR + c4 * 4] = vo;
        }
        __syncthreads();

        // ---- S strip [16 x 64] = Q @ K^T ----
        float s[8][4];
        #pragma unroll
        for (int n = 0; n < 8; n++) {
            s[n][0] = s[n][1] = s[n][2] = s[n][3] = 0.f;
            #pragma unroll
            for (int kt = 0; kt < 4; kt++) {
                uint32_t b0 = __float_as_uint(sK[(n * 8 + g) * STR + kt * 8 + q    ]);
                uint32_t b1 = __float_as_uint(sK[(n * 8 + g) * STR + kt * 8 + q + 4]);
                mma_tf32(s[n], qa[kt], b0, b1);
            }
        }

        // ---- Online softmax (rows g, g+8); quad-reduce via shfl ----
        float t0m = -1e30f, t1m = -1e30f;
        #pragma unroll
        for (int n = 0; n < 8; n++) {
            t0m = fmaxf(t0m, fmaxf(s[n][0], s[n][1]));
            t1m = fmaxf(t1m, fmaxf(s[n][2], s[n][3]));
        }
        t0m = fmaxf(t0m, __shfl_xor_sync(0xFFFFFFFF, t0m, 1));
        t0m = fmaxf(t0m, __shfl_xor_sync(0xFFFFFFFF, t0m, 2));
        t1m = fmaxf(t1m, __shfl_xor_sync(0xFFFFFFFF, t1m, 1));
        t1m = fmaxf(t1m, __shfl_xor_sync(0xFFFFFFFF, t1m, 2));

        float mn0 = fmaxf(m0, t0m), mn1 = fmaxf(m1, t1m);
        float c0 = __expf(m0 - mn0), c1 = __expf(m1 - mn1);
        float ps0 = 0.f, ps1 = 0.f;
        #pragma unroll
        for (int n = 0; n < 8; n++) {
            s[n][0] = __expf(s[n][0] - mn0);
            s[n][1] = __expf(s[n][1] - mn0);
            s[n][2] = __expf(s[n][2] - mn1);
            s[n][3] = __expf(s[n][3] - mn1);
            ps0 += s[n][0] + s[n][1];
            ps1 += s[n][2] + s[n][3];
        }
        ps0 += __shfl_xor_sync(0xFFFFFFFF, ps0, 1);
        ps0 += __shfl_xor_sync(0xFFFFFFFF, ps0, 2);
        ps1 += __shfl_xor_sync(0xFFFFFFFF, ps1, 1);
        ps1 += __shfl_xor_sync(0xFFFFFFFF, ps1, 2);
        l0 = l0 * c0 + ps0;  m0 = mn0;
        l1 = l1 * c1 + ps1;  m1 = mn1;

        // ---- Store P (tf32-rounded) to per-warp smem strip ----
        #pragma unroll
        for (int n = 0; n < 8; n++) {
            sP[(wr + g    ) * PSTR + n * 8 + 2 * q    ] = __uint_as_float(f2tf32(s[n][0]));
            sP[(wr + g    ) * PSTR + n * 8 + 2 * q + 1] = __uint_as_float(f2tf32(s[n][1]));
            sP[(wr + g + 8) * PSTR + n * 8 + 2 * q    ] = __uint_as_float(f2tf32(s[n][2]));
            sP[(wr + g + 8) * PSTR + n * 8 + 2 * q + 1] = __uint_as_float(f2tf32(s[n][3]));
        }
        __syncwarp();

        // ---- Rescale O, then O += P @ V ----
        #pragma unroll
        for (int n = 0; n < 4; n++) {
            o[n][0] *= c0; o[n][1] *= c0;
            o[n][2] *= c1; o[n][3] *= c1;
        }
        #pragma unroll
        for (int kt = 0; kt < 8; kt++) {
            uint32_t pa[4];
            pa[0] = __float_as_uint(sP[(wr + g    ) * PSTR + kt * 8 + q    ]);
            pa[1] = __float_as_uint(sP[(wr + g + 8) * PSTR + kt * 8 + q    ]);
            pa[2] = __float_as_uint(sP[(wr + g    ) * PSTR + kt * 8 + q + 4]);
            pa[3] = __float_as_uint(sP[(wr + g + 8) * PSTR + kt * 8 + q + 4]);
            #pragma unroll
            for (int n = 0; n < 4; n++) {
                uint32_t b0 = __float_as_uint(sV[(kt * 8 + q    ) * STR + n * 8 + g]);
                uint32_t b1 = __float_as_uint(sV[(kt * 8 + q + 4) * STR + n * 8 + g]);
                mma_tf32(o[n], pa, b0, b1);
            }
        }
        __syncwarp();
    }

    // ---- Epilogue: normalize, write O strip to g_O ----
    const float inv0 = 1.f / l0, inv1 = 1.f / l1;
    const int b = bh / HEADS, h = bh % HEADS;
    float* Og = g_O + ((size_t)(b * SEQ + q0 + wr)) * EMB + h * HDIM;
    #pragma unroll
    for (int n = 0; n < 4; n++) {
        float2 r0 = make_float2(o[n][0] * inv0, o[n][1] * inv0);
        float2 r1 = make_float2(o[n][2] * inv1, o[n][3] * inv1);
        *(float2*)(Og + (size_t)(g    ) * EMB + n * 8 + 2 * q) = r0;
        *(float2*)(Og + (size_t)(g + 8) * EMB + n * 8 + 2 * q) = r1;
    }
}

// ===========================================================================
// Output projection (fp32 tiled GEMM)
// ===========================================================================
__global__ __launch_bounds__(256) void proj_kernel(
    const float* __restrict__ Wo, const float* __restrict__ bo,
    float* __restrict__ out)
{
    __shared__ float As[BK][BM+SPAD];
    __shared__ float Ws[BK][BN+SPAD];

    const int tid = threadIdx.x;
    const int m0 = blockIdx.x * BM;
    const int n0 = blockIdx.y * BN;
    const int tx = tid & 15;
    const int ty = tid >> 4;

    float acc[4][4] = {};

    for (int k0 = 0; k0 < EMB; k0 += BK) {
        #pragma unroll
        for (int it = 0; it < 4; it++) {
            int i = it * 256 + tid;
            int m = i >> 4, k = i & 15;
            As[k][m] = g_O[(size_t)(m0 + m) * EMB + k0 + k];
        }
        #pragma unroll
        for (int it = 0; it < 4; it++) {
            int i = it * 256 + tid;
            int n = i >> 4, k = i & 15;
            Ws[k][n] = Wo[(size_t)(n0 + n) * EMB + k0 + k];
        }
        __syncthreads();
        #pragma unroll
        for (int k = 0; k < BK; k++) {
            float4 a4 = *(const float4*)&As[k][ty * 4];
            float4 w4 = *(const float4*)&Ws[k][tx * 4];
            float av[4] = {a4.x, a4.y, a4.z, a4.w};
            float wv[4] = {w4.x, w4.y, w4.z, w4.w};
            #pragma unroll
            for (int i = 0; i < 4; i++)
                #pragma unroll
                for (int j = 0; j < 4; j++)
                    acc[i][j] += av[i] * wv[j];
        }
        __syncthreads();
    }

    #pragma unroll
    for (int i = 0; i < 4; i++) {
        int gm = m0 + ty * 4 + i;
        #pragma unroll
        for (int j = 0; j < 4; j++) {
            int col = n0 + tx * 4 + j;
            out[(size_t)gm * EMB + col] = acc[i][j] + bo[col];
        }
    }
}

// ===========================================================================
extern "C" void kernel_launch(void* const* d_in, const int* in_sizes, int n_in,
                              void* d_out, int out_size)
{
    const float* x  = (const float*)d_in[0];
    const float* Wq = (const float*)d_in[1];
    const float* bq = (const float*)d_in[2];
    const float* Wk = (const float*)d_in[3];
    const float* bk = (const float*)d_in[4];
    const float* Wv = (const float*)d_in[5];
    const float* bv = (const float*)d_in[6];
    const float* Wo = (const float*)d_in[7];
    const float* bo = (const float*)d_in[8];
    float* out = (float*)d_out;

    dim3 gemm_grid(MROWS / BM, EMB / BN);   // (128, 4)
    qkv_kernel<<<gemm_grid, 256>>>(x, Wq, bq, Wk, bk, Wv, bv);

    dim3 attn_grid(SEQ / QT, BATCH * HEADS);  // (32, 32)
    attn_mma_kernel<<<attn_grid, 128>>>();

    proj_kernel<<<gemm_grid, 256>>>(Wo, bo, out);
}